// round 2
// baseline (speedup 1.0000x reference)
#include <cuda_runtime.h>
#include <math.h>

// Problem constants
// B=4, L=2048, HS=2048, NH=32, HD=64, K=16, NM=128, M = B*L = 8192

__device__ float g_Q[8192 * 2048];
__device__ float g_K[8192 * 2048];
__device__ float g_V[8192 * 2048];
__device__ float g_Y[8192 * 2048];
__device__ float g_LR[8192 * 32];

// ---------------------------------------------------------------------------
// SGEMM: C[m,n] = sum_k A[m,k] * W[n,k]   (A: MxKc row-major, W: NxKc row-major)
// 128x128 tile, BK=8, 256 threads, 8x8 per thread, register prefetch.
// ---------------------------------------------------------------------------
#define SM_BM 128
#define SM_BN 128
#define SM_BK 8

__global__ __launch_bounds__(256, 2) void sgemm_nt(
    const float* __restrict__ A, const float* __restrict__ W,
    float* __restrict__ C, int M, int N, int Kc)
{
    __shared__ __align__(16) float As[SM_BK][SM_BM];
    __shared__ __align__(16) float Bs[SM_BK][SM_BN];
    int tid = threadIdx.x;
    int bm = blockIdx.y * SM_BM;
    int bn = blockIdx.x * SM_BN;
    int lr = tid >> 1;            // 0..127 : row within tile
    int lc = (tid & 1) << 2;      // 0 or 4 : col within 8-wide k-slab
    const float* Ab = A + (size_t)(bm + lr) * Kc + lc;
    const float* Wb = W + (size_t)(bn + lr) * Kc + lc;
    int tx = tid & 15, ty = tid >> 4;

    float acc[8][8];
#pragma unroll
    for (int i = 0; i < 8; i++)
#pragma unroll
        for (int j = 0; j < 8; j++) acc[i][j] = 0.0f;

    float4 a_n = *(const float4*)Ab;
    float4 b_n = *(const float4*)Wb;

    for (int k0 = 0; k0 < Kc; k0 += SM_BK) {
        As[lc + 0][lr] = a_n.x; As[lc + 1][lr] = a_n.y;
        As[lc + 2][lr] = a_n.z; As[lc + 3][lr] = a_n.w;
        Bs[lc + 0][lr] = b_n.x; Bs[lc + 1][lr] = b_n.y;
        Bs[lc + 2][lr] = b_n.z; Bs[lc + 3][lr] = b_n.w;
        __syncthreads();
        if (k0 + SM_BK < Kc) {
            a_n = *(const float4*)(Ab + k0 + SM_BK);
            b_n = *(const float4*)(Wb + k0 + SM_BK);
        }
#pragma unroll
        for (int kk = 0; kk < SM_BK; kk++) {
            float ra[8], rb[8];
            *(float4*)&ra[0] = *(const float4*)&As[kk][ty * 8];
            *(float4*)&ra[4] = *(const float4*)&As[kk][ty * 8 + 4];
            *(float4*)&rb[0] = *(const float4*)&Bs[kk][tx * 8];
            *(float4*)&rb[4] = *(const float4*)&Bs[kk][tx * 8 + 4];
#pragma unroll
            for (int i = 0; i < 8; i++)
#pragma unroll
                for (int j = 0; j < 8; j++)
                    acc[i][j] += ra[i] * rb[j];
        }
        __syncthreads();
    }

#pragma unroll
    for (int i = 0; i < 8; i++) {
        float* crow = C + (size_t)(bm + ty * 8 + i) * N + bn + tx * 8;
        *(float4*)crow       = make_float4(acc[i][0], acc[i][1], acc[i][2], acc[i][3]);
        *(float4*)(crow + 4) = make_float4(acc[i][4], acc[i][5], acc[i][6], acc[i][7]);
    }
}

// ---------------------------------------------------------------------------
// ttt_lr projection: out[t, h] = dot(H[t,:2048], Wlr[h,:2048]) + lr_bias[h]
// block = 256 threads = 8 tokens x 32 heads
// ---------------------------------------------------------------------------
__global__ void lr_kernel(const float* __restrict__ H, const float* __restrict__ Wlr,
                          const float* __restrict__ lr_bias, float* __restrict__ out)
{
    int t = blockIdx.x * 8 + (threadIdx.x >> 5);
    int h = threadIdx.x & 31;
    const float* hrow = H + (size_t)t * 2048;
    const float* wrow = Wlr + (size_t)h * 2048;
    float acc = 0.0f;
    for (int c = 0; c < 2048; c += 4) {
        float4 hv = *(const float4*)(hrow + c);
        float4 wv = *(const float4*)(wrow + c);
        acc += hv.x * wv.x + hv.y * wv.y + hv.z * wv.z + hv.w * wv.w;
    }
    out[(size_t)t * 32 + h] = acc + lr_bias[h];
}

// ---------------------------------------------------------------------------
// Scan kernel: one CTA per (b,h) pair, loops over 128 minibatches.
// State W1 (64x64) + b1 (64) kept in shared memory.
// 256 threads: r = tid/16 in [0,16) row, g4 = (tid%16)*4 column quad.
// ---------------------------------------------------------------------------
__device__ __forceinline__ float rsum16(float v)
{
    v += __shfl_xor_sync(0xffffffffu, v, 1);
    v += __shfl_xor_sync(0xffffffffu, v, 2);
    v += __shfl_xor_sync(0xffffffffu, v, 4);
    v += __shfl_xor_sync(0xffffffffu, v, 8);
    return v;
}

__global__ __launch_bounds__(256, 1) void scan_kernel(
    const float* __restrict__ Q, const float* __restrict__ K_,
    const float* __restrict__ V, const float* __restrict__ LR,
    const float* __restrict__ W1_0, const float* __restrict__ b1_0,
    const float* __restrict__ lnw, const float* __restrict__ lnb,
    const float* __restrict__ ltk, float* __restrict__ Y)
{
    const int SD = 65;  // padded stride for 16x64 tiles (bank-conflict-free)
    __shared__ __align__(16) float W1[64 * 64];
    __shared__ float xq[16 * 65], xk[16 * 65], xv[16 * 65], gr[16 * 65];
    __shared__ float b1v[64], gam[64], bet[64];
    __shared__ float coef[256], evec[16], tok[16];

    int bh = blockIdx.x, b = bh >> 5, h = bh & 31;
    int tid = threadIdx.x;

    for (int i = tid; i < 4096; i += 256) W1[i] = W1_0[h * 4096 + i];
    if (tid < 64) {
        b1v[tid] = b1_0[h * 64 + tid];
        gam[tid] = lnw[h * 64 + tid];
        bet[tid] = lnb[h * 64 + tid];
    }
    if (tid < 16) tok[tid] = fmaxf(1.0f / (float)(tid + 1) + ltk[tid], 0.0f);
    __syncthreads();

    int r = tid >> 4;            // row 0..15
    int g4 = (tid & 15) << 2;    // col quad 0,4,...,60

    for (int nm = 0; nm < 128; nm++) {
        size_t base = ((size_t)b * 2048 + (size_t)nm * 16) * 2048 + (size_t)h * 64;
        // Load the 16x64 tiles (coalesced: 64 consecutive floats per row)
        for (int i = tid; i < 1024; i += 256) {
            int k = i >> 6, d = i & 63;
            size_t gi = base + (size_t)k * 2048 + d;
            xq[k * SD + d] = Q[gi];
            xk[k * SD + d] = K_[gi];
            xv[k * SD + d] = V[gi];
        }
        if (tid < 16) {
            float x = LR[((size_t)b * 2048 + (size_t)nm * 16 + tid) * 32 + h];
            evec[tid] = (1.0f / (1.0f + expf(-x))) * (1.0f / 64.0f);
        }
        __syncthreads();

        // Z1 = xk @ W1 + b1  and  qW = xq @ W1 + b1  (fused over shared W1 reads)
        float z[4], qw[4];
#pragma unroll
        for (int t = 0; t < 4; t++) { z[t] = b1v[g4 + t]; qw[t] = b1v[g4 + t]; }
        for (int c = 0; c < 64; c++) {
            float kc = xk[r * SD + c], qc = xq[r * SD + c];
            float4 w4 = *(const float4*)&W1[c * 64 + g4];
            z[0] += kc * w4.x; z[1] += kc * w4.y; z[2] += kc * w4.z; z[3] += kc * w4.w;
            qw[0] += qc * w4.x; qw[1] += qc * w4.y; qw[2] += qc * w4.z; qw[3] += qc * w4.w;
        }

        // grad = ln_fused_l2_bwd(Z1, xv - xk, gamma, beta)   (row-wise, D=64)
        float s = z[0] + z[1] + z[2] + z[3];
        s = rsum16(s);
        float mu = s * (1.0f / 64.0f);
        float xh[4]; float vs = 0.0f;
#pragma unroll
        for (int t = 0; t < 4; t++) { float d0 = z[t] - mu; xh[t] = d0; vs += d0 * d0; }
        vs = rsum16(vs);
        float stdv = sqrtf(vs * (1.0f / 64.0f) + 1e-6f);
        float rstd = 1.0f / stdv;
        float gxh[4]; float s1 = 0.0f, s2 = 0.0f;
#pragma unroll
        for (int t = 0; t < 4; t++) {
            xh[t] *= rstd;
            float tgt = xv[r * SD + g4 + t] - xk[r * SD + g4 + t];
            float gm = gam[g4 + t];
            gxh[t] = (gm * xh[t] + bet[g4 + t] - tgt) * gm;
            s1 += gxh[t]; s2 += gxh[t] * xh[t];
        }
        s1 = rsum16(s1);
        s2 = rsum16(s2);
        float c1 = rstd * (1.0f / 64.0f);
#pragma unroll
        for (int t = 0; t < 4; t++)
            gr[r * SD + g4 + t] = (64.0f * gxh[t] - s1 - xh[t] * s2) * c1;
        __syncthreads();

        // Attn1[i,j] = xq[i]·xk[j]; combined coefficient
        // coef[i,j] = tok[i]*e[j]*(1+Attn[i,j]) for j<=i else 0
        {
            int i = r, j = tid & 15;
            float a = 0.0f;
            for (int c = 0; c < 64; c++) a += xq[i * SD + c] * xk[j * SD + c];
            coef[i * 16 + j] = (j <= i) ? tok[i] * evec[j] * (1.0f + a) : 0.0f;
        }
        __syncthreads();

        // Z1_bar = xq@W1 + b1 - coef @ grad ; out = xq + LN(Z1_bar)
        float zb[4] = {qw[0], qw[1], qw[2], qw[3]};
        for (int j = 0; j < 16; j++) {
            float cf = coef[r * 16 + j];
            zb[0] -= cf * gr[j * SD + g4 + 0];
            zb[1] -= cf * gr[j * SD + g4 + 1];
            zb[2] -= cf * gr[j * SD + g4 + 2];
            zb[3] -= cf * gr[j * SD + g4 + 3];
        }
        float s0 = zb[0] + zb[1] + zb[2] + zb[3];
        s0 = rsum16(s0);
        float mu2 = s0 * (1.0f / 64.0f);
        float v2 = 0.0f;
#pragma unroll
        for (int t = 0; t < 4; t++) { float d0 = zb[t] - mu2; v2 += d0 * d0; }
        v2 = rsum16(v2);
        float rstd2 = rsqrtf(v2 * (1.0f / 64.0f) + 1e-6f);
        {
            float o0 = xq[r * SD + g4 + 0] + gam[g4 + 0] * ((zb[0] - mu2) * rstd2) + bet[g4 + 0];
            float o1 = xq[r * SD + g4 + 1] + gam[g4 + 1] * ((zb[1] - mu2) * rstd2) + bet[g4 + 1];
            float o2 = xq[r * SD + g4 + 2] + gam[g4 + 2] * ((zb[2] - mu2) * rstd2) + bet[g4 + 2];
            float o3 = xq[r * SD + g4 + 3] + gam[g4 + 3] * ((zb[3] - mu2) * rstd2) + bet[g4 + 3];
            *(float4*)&Y[base + (size_t)r * 2048 + g4] = make_float4(o0, o1, o2, o3);
        }
        __syncthreads();

        // Scale grad rows by last_eta[j] = tok[15]*e[j]
        for (int i = tid; i < 1024; i += 256) {
            int j = i >> 6, d = i & 63;
            gr[j * SD + d] *= tok[15] * evec[j];
        }
        __syncthreads();

        // W1 -= xk^T @ gr_scaled ;  b1 -= colsum(gr_scaled)
#pragma unroll
        for (int cc = 0; cc < 4; cc++) {
            int c = r + cc * 16;
            float4* wp = (float4*)&W1[c * 64 + g4];
            float4 w = *wp;
#pragma unroll
            for (int j = 0; j < 16; j++) {
                float xkc = xk[j * SD + c];
                w.x -= xkc * gr[j * SD + g4 + 0];
                w.y -= xkc * gr[j * SD + g4 + 1];
                w.z -= xkc * gr[j * SD + g4 + 2];
                w.w -= xkc * gr[j * SD + g4 + 3];
            }
            *wp = w;
        }
        if (tid < 64) {
            float bb = b1v[tid];
#pragma unroll
            for (int j = 0; j < 16; j++) bb -= gr[j * SD + tid];
            b1v[tid] = bb;
        }
        __syncthreads();
    }
}

// ---------------------------------------------------------------------------
// Post layernorm over HS=2048, in place on Y. One block per token.
// ---------------------------------------------------------------------------
__global__ void postln_kernel(float* __restrict__ Y,
                              const float* __restrict__ w, const float* __restrict__ b)
{
    int t = blockIdx.x;
    float* row = Y + (size_t)t * 2048;
    __shared__ float rs[8], rss[8], mv[2];
    int tid = threadIdx.x;
    float v[8]; float s = 0.0f, ss = 0.0f;
#pragma unroll
    for (int i = 0; i < 8; i++) {
        v[i] = row[tid + i * 256];
        s += v[i]; ss += v[i] * v[i];
    }
#pragma unroll
    for (int m = 16; m >= 1; m >>= 1) {
        s  += __shfl_xor_sync(0xffffffffu, s, m);
        ss += __shfl_xor_sync(0xffffffffu, ss, m);
    }
    if ((tid & 31) == 0) { rs[tid >> 5] = s; rss[tid >> 5] = ss; }
    __syncthreads();
    if (tid == 0) {
        float a = 0.0f, c = 0.0f;
        for (int i = 0; i < 8; i++) { a += rs[i]; c += rss[i]; }
        float mu = a * (1.0f / 2048.0f);
        float var = c * (1.0f / 2048.0f) - mu * mu;
        mv[0] = mu; mv[1] = rsqrtf(var + 1e-6f);
    }
    __syncthreads();
    float mu = mv[0], rstd = mv[1];
#pragma unroll
    for (int i = 0; i < 8; i++) {
        int d = tid + i * 256;
        row[d] = w[d] * ((v[i] - mu) * rstd) + b[d];
    }
}

// ---------------------------------------------------------------------------
extern "C" void kernel_launch(void* const* d_in, const int* in_sizes, int n_in,
                              void* d_out, int out_size)
{
    const float* hidden = (const float*)d_in[0];
    // d_in[1] = position_ids (unused)
    const float* q_w  = (const float*)d_in[2];
    const float* k_w  = (const float*)d_in[3];
    const float* v_w  = (const float*)d_in[4];
    const float* o_w  = (const float*)d_in[5];
    const float* W1_0 = (const float*)d_in[6];
    const float* b1_0 = (const float*)d_in[7];
    const float* lnw  = (const float*)d_in[8];
    const float* lnb  = (const float*)d_in[9];
    const float* lr_w = (const float*)d_in[10];
    const float* lr_b = (const float*)d_in[11];
    const float* ltk  = (const float*)d_in[12];
    const float* pnw  = (const float*)d_in[13];
    const float* pnb  = (const float*)d_in[14];
    float* out = (float*)d_out;

    float *Qp, *Kp, *Vp, *Yp, *LRp;
    cudaGetSymbolAddress((void**)&Qp,  g_Q);
    cudaGetSymbolAddress((void**)&Kp,  g_K);
    cudaGetSymbolAddress((void**)&Vp,  g_V);
    cudaGetSymbolAddress((void**)&Yp,  g_Y);
    cudaGetSymbolAddress((void**)&LRp, g_LR);

    dim3 gg(2048 / SM_BN, 8192 / SM_BM);
    sgemm_nt<<<gg, 256>>>(hidden, q_w, Qp, 8192, 2048, 2048);
    sgemm_nt<<<gg, 256>>>(hidden, k_w, Kp, 8192, 2048, 2048);
    sgemm_nt<<<gg, 256>>>(hidden, v_w, Vp, 8192, 2048, 2048);
    lr_kernel<<<1024, 256>>>(hidden, lr_w, lr_b, LRp);
    scan_kernel<<<128, 256>>>(Qp, Kp, Vp, LRp, W1_0, b1_0, lnw, lnb, ltk, Yp);
    postln_kernel<<<8192, 256>>>(Yp, pnw, pnb);
    sgemm_nt<<<gg, 256>>>(Yp, o_w, out, 8192, 2048, 2048);
}

// round 4
// speedup vs baseline: 2.1600x; 2.1600x over previous
#include <cuda_runtime.h>
#include <math.h>
#include <stdint.h>

// Problem constants: B=4, L=2048, HS=2048, NH=32, HD=64, K=16, NM=128, M=B*L=8192

__device__ float g_Q[8192 * 2048];
__device__ float g_K[8192 * 2048];
__device__ float g_V[8192 * 2048];
__device__ float g_Y[8192 * 2048];
__device__ float g_LR[8192 * 32];

// ---------------------------------------------------------------------------
// TF32 tensor-core GEMM: C[m,n] = sum_k A[m,k] * W[n,k]
// A: MxKc row-major, W: NxKc row-major. 128x128 tile, BK=16, 256 threads.
// Inputs converted f32->tf32 with cvt.rna (round-to-nearest) to avoid bias.
// ---------------------------------------------------------------------------
__device__ __forceinline__ uint32_t f2tf(float x) {
    uint32_t r;
    asm("cvt.rna.tf32.f32 %0, %1;" : "=r"(r) : "f"(x));
    return r;
}

__device__ __forceinline__ void mma_tf32(float* c, const uint32_t* a, const uint32_t* b) {
    asm volatile(
        "mma.sync.aligned.m16n8k8.row.col.f32.tf32.tf32.f32 "
        "{%0,%1,%2,%3}, {%4,%5,%6,%7}, {%8,%9}, {%0,%1,%2,%3};"
        : "+f"(c[0]), "+f"(c[1]), "+f"(c[2]), "+f"(c[3])
        : "r"(a[0]), "r"(a[1]), "r"(a[2]), "r"(a[3]), "r"(b[0]), "r"(b[1]));
}

#define GSD 136  // padded stride: bank = tig*8+gid, conflict-free

__global__ __launch_bounds__(256, 2) void gemm_tf32_nt(
    const float* __restrict__ A, const float* __restrict__ W,
    float* __restrict__ C, int M, int N, int Kc)
{
    __shared__ __align__(16) uint32_t As[2][16][GSD];
    __shared__ __align__(16) uint32_t Bs[2][16][GSD];

    int tid = threadIdx.x;
    int bm = blockIdx.y * 128, bn = blockIdx.x * 128;
    int warp = tid >> 5, lane = tid & 31;
    int gid = lane >> 2, tig = lane & 3;
    int wm = (warp & 1) * 64, wn = (warp >> 1) * 32;

    // tile loader mapping: thread handles rows jm and jm+64, k-quad jk
    int jm = tid >> 2, jk = (tid & 3) << 2;
    const float* Ar0 = A + (size_t)(bm + jm) * Kc + jk;
    const float* Ar1 = A + (size_t)(bm + jm + 64) * Kc + jk;
    const float* Wr0 = W + (size_t)(bn + jm) * Kc + jk;
    const float* Wr1 = W + (size_t)(bn + jm + 64) * Kc + jk;

    float acc[4][4][4];
#pragma unroll
    for (int mi = 0; mi < 4; mi++)
#pragma unroll
        for (int ni = 0; ni < 4; ni++)
#pragma unroll
            for (int t = 0; t < 4; t++) acc[mi][ni][t] = 0.0f;

    float4 pa0 = *(const float4*)Ar0;
    float4 pa1 = *(const float4*)Ar1;
    float4 pb0 = *(const float4*)Wr0;
    float4 pb1 = *(const float4*)Wr1;

    // store tile 0
    As[0][jk + 0][jm] = f2tf(pa0.x); As[0][jk + 1][jm] = f2tf(pa0.y);
    As[0][jk + 2][jm] = f2tf(pa0.z); As[0][jk + 3][jm] = f2tf(pa0.w);
    As[0][jk + 0][jm + 64] = f2tf(pa1.x); As[0][jk + 1][jm + 64] = f2tf(pa1.y);
    As[0][jk + 2][jm + 64] = f2tf(pa1.z); As[0][jk + 3][jm + 64] = f2tf(pa1.w);
    Bs[0][jk + 0][jm] = f2tf(pb0.x); Bs[0][jk + 1][jm] = f2tf(pb0.y);
    Bs[0][jk + 2][jm] = f2tf(pb0.z); Bs[0][jk + 3][jm] = f2tf(pb0.w);
    Bs[0][jk + 0][jm + 64] = f2tf(pb1.x); Bs[0][jk + 1][jm + 64] = f2tf(pb1.y);
    Bs[0][jk + 2][jm + 64] = f2tf(pb1.z); Bs[0][jk + 3][jm + 64] = f2tf(pb1.w);
    __syncthreads();

    int nk = Kc >> 4;
    for (int kt = 0; kt < nk; kt++) {
        int cur = kt & 1;
        if (kt + 1 < nk) {
            int off = (kt + 1) << 4;
            pa0 = *(const float4*)(Ar0 + off);
            pa1 = *(const float4*)(Ar1 + off);
            pb0 = *(const float4*)(Wr0 + off);
            pb1 = *(const float4*)(Wr1 + off);
        }
#pragma unroll
        for (int ks = 0; ks < 2; ks++) {
            int k8 = ks * 8;
            uint32_t a[4][4], b[4][2];
#pragma unroll
            for (int mi = 0; mi < 4; mi++) {
                int m0 = wm + mi * 16 + gid;
                a[mi][0] = As[cur][k8 + tig][m0];
                a[mi][1] = As[cur][k8 + tig][m0 + 8];
                a[mi][2] = As[cur][k8 + tig + 4][m0];
                a[mi][3] = As[cur][k8 + tig + 4][m0 + 8];
            }
#pragma unroll
            for (int ni = 0; ni < 4; ni++) {
                int n0 = wn + ni * 8 + gid;
                b[ni][0] = Bs[cur][k8 + tig][n0];
                b[ni][1] = Bs[cur][k8 + tig + 4][n0];
            }
#pragma unroll
            for (int mi = 0; mi < 4; mi++)
#pragma unroll
                for (int ni = 0; ni < 4; ni++)
                    mma_tf32(acc[mi][ni], a[mi], b[ni]);
        }
        if (kt + 1 < nk) {
            int nb = cur ^ 1;
            As[nb][jk + 0][jm] = f2tf(pa0.x); As[nb][jk + 1][jm] = f2tf(pa0.y);
            As[nb][jk + 2][jm] = f2tf(pa0.z); As[nb][jk + 3][jm] = f2tf(pa0.w);
            As[nb][jk + 0][jm + 64] = f2tf(pa1.x); As[nb][jk + 1][jm + 64] = f2tf(pa1.y);
            As[nb][jk + 2][jm + 64] = f2tf(pa1.z); As[nb][jk + 3][jm + 64] = f2tf(pa1.w);
            Bs[nb][jk + 0][jm] = f2tf(pb0.x); Bs[nb][jk + 1][jm] = f2tf(pb0.y);
            Bs[nb][jk + 2][jm] = f2tf(pb0.z); Bs[nb][jk + 3][jm] = f2tf(pb0.w);
            Bs[nb][jk + 0][jm + 64] = f2tf(pb1.x); Bs[nb][jk + 1][jm + 64] = f2tf(pb1.y);
            Bs[nb][jk + 2][jm + 64] = f2tf(pb1.z); Bs[nb][jk + 3][jm + 64] = f2tf(pb1.w);
        }
        __syncthreads();
    }

    // epilogue: c0,c1 at (gid, 2*tig..+1); c2,c3 at (gid+8, ...)
#pragma unroll
    for (int mi = 0; mi < 4; mi++) {
#pragma unroll
        for (int ni = 0; ni < 4; ni++) {
            int row0 = bm + wm + mi * 16 + gid;
            int col = bn + wn + ni * 8 + tig * 2;
            float2 v0 = make_float2(acc[mi][ni][0], acc[mi][ni][1]);
            float2 v1 = make_float2(acc[mi][ni][2], acc[mi][ni][3]);
            *(float2*)(C + (size_t)row0 * N + col) = v0;
            *(float2*)(C + (size_t)(row0 + 8) * N + col) = v1;
        }
    }
}

// ---------------------------------------------------------------------------
// ttt_lr projection: out[t,h] = dot(H[t,:2048], Wlr[h,:2048]) + lr_bias[h]
// warp per token, lanes span columns (coalesced H and W), 32 head accumulators
// ---------------------------------------------------------------------------
__global__ __launch_bounds__(256) void lr_kernel(
    const float* __restrict__ H, const float* __restrict__ Wlr,
    const float* __restrict__ lr_bias, float* __restrict__ out)
{
    int warp = threadIdx.x >> 5, lane = threadIdx.x & 31;
    int t = blockIdx.x * 8 + warp;
    const float* hrow = H + (size_t)t * 2048;
    float acc[32];
#pragma unroll
    for (int h = 0; h < 32; h++) acc[h] = 0.0f;

    for (int c0 = lane * 4; c0 < 2048; c0 += 128) {
        float4 hv = *(const float4*)(hrow + c0);
#pragma unroll
        for (int h = 0; h < 32; h++) {
            float4 wv = *(const float4*)(Wlr + (size_t)h * 2048 + c0);
            acc[h] += hv.x * wv.x + hv.y * wv.y + hv.z * wv.z + hv.w * wv.w;
        }
    }
#pragma unroll
    for (int h = 0; h < 32; h++) {
        float v = acc[h];
        v += __shfl_xor_sync(0xffffffffu, v, 16);
        v += __shfl_xor_sync(0xffffffffu, v, 8);
        v += __shfl_xor_sync(0xffffffffu, v, 4);
        v += __shfl_xor_sync(0xffffffffu, v, 2);
        v += __shfl_xor_sync(0xffffffffu, v, 1);
        if (lane == h) out[(size_t)t * 32 + h] = v + lr_bias[h];
    }
}

// ---------------------------------------------------------------------------
// Scan kernel: one CTA per (b,h) pair, loops over 128 minibatches.
// ---------------------------------------------------------------------------
__device__ __forceinline__ float rsum16(float v)
{
    v += __shfl_xor_sync(0xffffffffu, v, 1);
    v += __shfl_xor_sync(0xffffffffu, v, 2);
    v += __shfl_xor_sync(0xffffffffu, v, 4);
    v += __shfl_xor_sync(0xffffffffu, v, 8);
    return v;
}

__global__ __launch_bounds__(256, 1) void scan_kernel(
    const float* __restrict__ Q, const float* __restrict__ K_,
    const float* __restrict__ V, const float* __restrict__ LR,
    const float* __restrict__ W1_0, const float* __restrict__ b1_0,
    const float* __restrict__ lnw, const float* __restrict__ lnb,
    const float* __restrict__ ltk, float* __restrict__ Y)
{
    const int SD = 65;
    __shared__ __align__(16) float W1[64 * 64];
    __shared__ float xq[16 * 65], xk[16 * 65], xv[16 * 65], gr[16 * 65];
    __shared__ float b1v[64], gam[64], bet[64];
    __shared__ float coef[256], evec[16], tok[16];

    int bh = blockIdx.x, b = bh >> 5, h = bh & 31;
    int tid = threadIdx.x;

    for (int i = tid; i < 4096; i += 256) W1[i] = W1_0[h * 4096 + i];
    if (tid < 64) {
        b1v[tid] = b1_0[h * 64 + tid];
        gam[tid] = lnw[h * 64 + tid];
        bet[tid] = lnb[h * 64 + tid];
    }
    if (tid < 16) tok[tid] = fmaxf(1.0f / (float)(tid + 1) + ltk[tid], 0.0f);
    __syncthreads();

    int r = tid >> 4;
    int g4 = (tid & 15) << 2;

    for (int nm = 0; nm < 128; nm++) {
        size_t base = ((size_t)b * 2048 + (size_t)nm * 16) * 2048 + (size_t)h * 64;
        for (int i = tid; i < 1024; i += 256) {
            int k = i >> 6, d = i & 63;
            size_t gi = base + (size_t)k * 2048 + d;
            xq[k * SD + d] = Q[gi];
            xk[k * SD + d] = K_[gi];
            xv[k * SD + d] = V[gi];
        }
        if (tid < 16) {
            float x = LR[((size_t)b * 2048 + (size_t)nm * 16 + tid) * 32 + h];
            evec[tid] = (1.0f / (1.0f + expf(-x))) * (1.0f / 64.0f);
        }
        __syncthreads();

        float z[4], qw[4];
#pragma unroll
        for (int t = 0; t < 4; t++) { z[t] = b1v[g4 + t]; qw[t] = b1v[g4 + t]; }
        for (int c = 0; c < 64; c++) {
            float kc = xk[r * SD + c], qc = xq[r * SD + c];
            float4 w4 = *(const float4*)&W1[c * 64 + g4];
            z[0] += kc * w4.x; z[1] += kc * w4.y; z[2] += kc * w4.z; z[3] += kc * w4.w;
            qw[0] += qc * w4.x; qw[1] += qc * w4.y; qw[2] += qc * w4.z; qw[3] += qc * w4.w;
        }

        float s = z[0] + z[1] + z[2] + z[3];
        s = rsum16(s);
        float mu = s * (1.0f / 64.0f);
        float xh[4]; float vs = 0.0f;
#pragma unroll
        for (int t = 0; t < 4; t++) { float d0 = z[t] - mu; xh[t] = d0; vs += d0 * d0; }
        vs = rsum16(vs);
        float rstd = 1.0f / sqrtf(vs * (1.0f / 64.0f) + 1e-6f);
        float gxh[4]; float s1 = 0.0f, s2 = 0.0f;
#pragma unroll
        for (int t = 0; t < 4; t++) {
            xh[t] *= rstd;
            float tgt = xv[r * SD + g4 + t] - xk[r * SD + g4 + t];
            float gm = gam[g4 + t];
            gxh[t] = (gm * xh[t] + bet[g4 + t] - tgt) * gm;
            s1 += gxh[t]; s2 += gxh[t] * xh[t];
        }
        s1 = rsum16(s1);
        s2 = rsum16(s2);
        float c1 = rstd * (1.0f / 64.0f);
#pragma unroll
        for (int t = 0; t < 4; t++)
            gr[r * SD + g4 + t] = (64.0f * gxh[t] - s1 - xh[t] * s2) * c1;
        __syncthreads();

        {
            int i = r, j = tid & 15;
            float a = 0.0f;
            for (int c = 0; c < 64; c++) a += xq[i * SD + c] * xk[j * SD + c];
            coef[i * 16 + j] = (j <= i) ? tok[i] * evec[j] * (1.0f + a) : 0.0f;
        }
        __syncthreads();

        float zb[4] = {qw[0], qw[1], qw[2], qw[3]};
        for (int j = 0; j < 16; j++) {
            float cf = coef[r * 16 + j];
            zb[0] -= cf * gr[j * SD + g4 + 0];
            zb[1] -= cf * gr[j * SD + g4 + 1];
            zb[2] -= cf * gr[j * SD + g4 + 2];
            zb[3] -= cf * gr[j * SD + g4 + 3];
        }
        float s0 = zb[0] + zb[1] + zb[2] + zb[3];
        s0 = rsum16(s0);
        float mu2 = s0 * (1.0f / 64.0f);
        float v2 = 0.0f;
#pragma unroll
        for (int t = 0; t < 4; t++) { float d0 = zb[t] - mu2; v2 += d0 * d0; }
        v2 = rsum16(v2);
        float rstd2 = rsqrtf(v2 * (1.0f / 64.0f) + 1e-6f);
        {
            float o0 = xq[r * SD + g4 + 0] + gam[g4 + 0] * ((zb[0] - mu2) * rstd2) + bet[g4 + 0];
            float o1 = xq[r * SD + g4 + 1] + gam[g4 + 1] * ((zb[1] - mu2) * rstd2) + bet[g4 + 1];
            float o2 = xq[r * SD + g4 + 2] + gam[g4 + 2] * ((zb[2] - mu2) * rstd2) + bet[g4 + 2];
            float o3 = xq[r * SD + g4 + 3] + gam[g4 + 3] * ((zb[3] - mu2) * rstd2) + bet[g4 + 3];
            *(float4*)&Y[base + (size_t)r * 2048 + g4] = make_float4(o0, o1, o2, o3);
        }
        __syncthreads();

        for (int i = tid; i < 1024; i += 256) {
            int j = i >> 6, d = i & 63;
            gr[j * SD + d] *= tok[15] * evec[j];
        }
        __syncthreads();

#pragma unroll
        for (int cc = 0; cc < 4; cc++) {
            int c = r + cc * 16;
            float4* wp = (float4*)&W1[c * 64 + g4];
            float4 w = *wp;
#pragma unroll
            for (int j = 0; j < 16; j++) {
                float xkc = xk[j * SD + c];
                w.x -= xkc * gr[j * SD + g4 + 0];
                w.y -= xkc * gr[j * SD + g4 + 1];
                w.z -= xkc * gr[j * SD + g4 + 2];
                w.w -= xkc * gr[j * SD + g4 + 3];
            }
            *wp = w;
        }
        if (tid < 64) {
            float bb = b1v[tid];
#pragma unroll
            for (int j = 0; j < 16; j++) bb -= gr[j * SD + tid];
            b1v[tid] = bb;
        }
        __syncthreads();
    }
}

// ---------------------------------------------------------------------------
// Post layernorm over HS=2048, in place on Y. One block per token.
// ---------------------------------------------------------------------------
__global__ void postln_kernel(float* __restrict__ Y,
                              const float* __restrict__ w, const float* __restrict__ b)
{
    int t = blockIdx.x;
    float* row = Y + (size_t)t * 2048;
    __shared__ float rs[8], rss[8], mv[2];
    int tid = threadIdx.x;
    float v[8]; float s = 0.0f, ss = 0.0f;
#pragma unroll
    for (int i = 0; i < 8; i++) {
        v[i] = row[tid + i * 256];
        s += v[i]; ss += v[i] * v[i];
    }
#pragma unroll
    for (int m = 16; m >= 1; m >>= 1) {
        s  += __shfl_xor_sync(0xffffffffu, s, m);
        ss += __shfl_xor_sync(0xffffffffu, ss, m);
    }
    if ((tid & 31) == 0) { rs[tid >> 5] = s; rss[tid >> 5] = ss; }
    __syncthreads();
    if (tid == 0) {
        float a = 0.0f, c = 0.0f;
        for (int i = 0; i < 8; i++) { a += rs[i]; c += rss[i]; }
        float mu = a * (1.0f / 2048.0f);
        float var = c * (1.0f / 2048.0f) - mu * mu;
        mv[0] = mu; mv[1] = rsqrtf(var + 1e-6f);
    }
    __syncthreads();
    float mu = mv[0], rstd = mv[1];
#pragma unroll
    for (int i = 0; i < 8; i++) {
        int d = tid + i * 256;
        row[d] = w[d] * ((v[i] - mu) * rstd) + b[d];
    }
}

// ---------------------------------------------------------------------------
extern "C" void kernel_launch(void* const* d_in, const int* in_sizes, int n_in,
                              void* d_out, int out_size)
{
    const float* hidden = (const float*)d_in[0];
    const float* q_w  = (const float*)d_in[2];
    const float* k_w  = (const float*)d_in[3];
    const float* v_w  = (const float*)d_in[4];
    const float* o_w  = (const float*)d_in[5];
    const float* W1_0 = (const float*)d_in[6];
    const float* b1_0 = (const float*)d_in[7];
    const float* lnw  = (const float*)d_in[8];
    const float* lnb  = (const float*)d_in[9];
    const float* lr_w = (const float*)d_in[10];
    const float* lr_b = (const float*)d_in[11];
    const float* ltk  = (const float*)d_in[12];
    const float* pnw  = (const float*)d_in[13];
    const float* pnb  = (const float*)d_in[14];
    float* out = (float*)d_out;

    float *Qp, *Kp, *Vp, *Yp, *LRp;
    cudaGetSymbolAddress((void**)&Qp,  g_Q);
    cudaGetSymbolAddress((void**)&Kp,  g_K);
    cudaGetSymbolAddress((void**)&Vp,  g_V);
    cudaGetSymbolAddress((void**)&Yp,  g_Y);
    cudaGetSymbolAddress((void**)&LRp, g_LR);

    dim3 gg(2048 / 128, 8192 / 128);
    gemm_tf32_nt<<<gg, 256>>>(hidden, q_w, Qp, 8192, 2048, 2048);
    gemm_tf32_nt<<<gg, 256>>>(hidden, k_w, Kp, 8192, 2048, 2048);
    gemm_tf32_nt<<<gg, 256>>>(hidden, v_w, Vp, 8192, 2048, 2048);
    lr_kernel<<<1024, 256>>>(hidden, lr_w, lr_b, LRp);
    scan_kernel<<<128, 256>>>(Qp, Kp, Vp, LRp, W1_0, b1_0, lnw, lnb, ltk, Yp);
    postln_kernel<<<8192, 256>>>(Yp, pnw, pnb);
    gemm_tf32_nt<<<gg, 256>>>(Yp, o_w, out, 8192, 2048, 2048);
}